// round 1
// baseline (speedup 1.0000x reference)
#include <cuda_runtime.h>
#include <cstdint>

// Problem constants
#define M_SLOTS 10
#define HW      7744          // 88*88
#define HW4     1936          // HW/4
#define ROWS    8192          // B*C = 32*256
#define KC      968           // chunk length (floats), HW = 8 * 968
#define KC4     242           // chunk length in float4
#define NCHUNK  8
#define RPB     32            // rows per block
#define NTHREADS 256
#define RPW     4             // rows per warp (8 warps * 4 = 32)

__device__ __forceinline__ unsigned long long fma2(unsigned long long a,
                                                   unsigned long long b,
                                                   unsigned long long c) {
    unsigned long long d;
    asm("fma.rn.f32x2 %0, %1, %2, %3;" : "=l"(d) : "l"(a), "l"(b), "l"(c));
    return d;
}

__global__ __launch_bounds__(NTHREADS, 2)
void memaug_fused_kernel(const float* __restrict__ x,
                         const float* __restrict__ mem,
                         float* __restrict__ out) {
    __shared__ float4 smem_w[M_SLOTS][KC4];     // 38,720 B mem chunk
    __shared__ float  p_smem[RPB][M_SLOTS];     // scores -> probabilities

    const int tid  = threadIdx.x;
    const int lane = tid & 31;
    const int warp = tid >> 5;
    const int row0 = blockIdx.x * RPB + warp * RPW;

    const float4* __restrict__ mem4 = (const float4*)mem;

    const float4* __restrict__ xr0 = (const float4*)(x + (size_t)(row0 + 0) * HW);
    const float4* __restrict__ xr1 = (const float4*)(x + (size_t)(row0 + 1) * HW);
    const float4* __restrict__ xr2 = (const float4*)(x + (size_t)(row0 + 2) * HW);
    const float4* __restrict__ xr3 = (const float4*)(x + (size_t)(row0 + 3) * HW);

    // ---------------- Phase 1: score[r][m] = <x_r, mem_m> ----------------
    float acc[RPW][M_SLOTS];
    #pragma unroll
    for (int r = 0; r < RPW; r++)
        #pragma unroll
        for (int m = 0; m < M_SLOTS; m++) acc[r][m] = 0.0f;

    for (int c = 0; c < NCHUNK; c++) {
        // cooperative chunk load: mem[m][c*KC .. c*KC+KC)
        for (int idx = tid; idx < M_SLOTS * KC4; idx += NTHREADS) {
            int m = idx / KC4;
            int j = idx - m * KC4;
            smem_w[m][j] = mem4[(size_t)m * HW4 + c * KC4 + j];
        }
        __syncthreads();

        const int base = c * KC4;
        for (int j = lane; j < KC4; j += 32) {
            float4 x0 = xr0[base + j];
            float4 x1 = xr1[base + j];
            float4 x2 = xr2[base + j];
            float4 x3 = xr3[base + j];
            #pragma unroll
            for (int m = 0; m < M_SLOTS; m++) {
                float4 w = smem_w[m][j];
                acc[0][m] = fmaf(x0.x, w.x, fmaf(x0.y, w.y, fmaf(x0.z, w.z, fmaf(x0.w, w.w, acc[0][m]))));
                acc[1][m] = fmaf(x1.x, w.x, fmaf(x1.y, w.y, fmaf(x1.z, w.z, fmaf(x1.w, w.w, acc[1][m]))));
                acc[2][m] = fmaf(x2.x, w.x, fmaf(x2.y, w.y, fmaf(x2.z, w.z, fmaf(x2.w, w.w, acc[2][m]))));
                acc[3][m] = fmaf(x3.x, w.x, fmaf(x3.y, w.y, fmaf(x3.z, w.z, fmaf(x3.w, w.w, acc[3][m]))));
            }
        }
        __syncthreads();
    }

    // warp-reduce the 40 partial dots, lane 0 stores scores
    #pragma unroll
    for (int r = 0; r < RPW; r++) {
        #pragma unroll
        for (int m = 0; m < M_SLOTS; m++) {
            float v = acc[r][m];
            v += __shfl_xor_sync(0xFFFFFFFFu, v, 16);
            v += __shfl_xor_sync(0xFFFFFFFFu, v, 8);
            v += __shfl_xor_sync(0xFFFFFFFFu, v, 4);
            v += __shfl_xor_sync(0xFFFFFFFFu, v, 2);
            v += __shfl_xor_sync(0xFFFFFFFFu, v, 1);
            if (lane == 0) p_smem[warp * RPW + r][m] = v;
        }
    }
    __syncthreads();

    // ---------------- softmax over m (one thread per row) ----------------
    if (tid < RPB) {
        float s[M_SLOTS];
        float mx = -1e30f;
        #pragma unroll
        for (int m = 0; m < M_SLOTS; m++) {
            s[m] = p_smem[tid][m];
            mx = fmaxf(mx, s[m]);
        }
        float sum = 0.0f;
        #pragma unroll
        for (int m = 0; m < M_SLOTS; m++) {
            s[m] = __expf(s[m] - mx);
            sum += s[m];
        }
        float inv = 1.0f / sum;
        #pragma unroll
        for (int m = 0; m < M_SLOTS; m++) p_smem[tid][m] = s[m] * inv;
    }
    __syncthreads();

    // ---------------- Phase 2: out_r = sum_m p[r][m] * mem_m (f32x2) -----
    unsigned long long p2[RPW][M_SLOTS];
    #pragma unroll
    for (int r = 0; r < RPW; r++) {
        #pragma unroll
        for (int m = 0; m < M_SLOTS; m++) {
            float pv = p_smem[warp * RPW + r][m];
            unsigned long long t;
            asm("mov.b64 %0, {%1, %1};" : "=l"(t) : "f"(pv));
            p2[r][m] = t;
        }
    }

    ulonglong2* __restrict__ or0 = (ulonglong2*)(out + (size_t)(row0 + 0) * HW);
    ulonglong2* __restrict__ or1 = (ulonglong2*)(out + (size_t)(row0 + 1) * HW);
    ulonglong2* __restrict__ or2 = (ulonglong2*)(out + (size_t)(row0 + 2) * HW);
    ulonglong2* __restrict__ or3 = (ulonglong2*)(out + (size_t)(row0 + 3) * HW);

    for (int c = 0; c < NCHUNK; c++) {
        for (int idx = tid; idx < M_SLOTS * KC4; idx += NTHREADS) {
            int m = idx / KC4;
            int j = idx - m * KC4;
            smem_w[m][j] = mem4[(size_t)m * HW4 + c * KC4 + j];
        }
        __syncthreads();

        const int base = c * KC4;
        for (int j = lane; j < KC4; j += 32) {
            unsigned long long o0a = 0ull, o0b = 0ull;
            unsigned long long o1a = 0ull, o1b = 0ull;
            unsigned long long o2a = 0ull, o2b = 0ull;
            unsigned long long o3a = 0ull, o3b = 0ull;
            #pragma unroll
            for (int m = 0; m < M_SLOTS; m++) {
                ulonglong2 w = *(const ulonglong2*)&smem_w[m][j];
                o0a = fma2(p2[0][m], w.x, o0a);  o0b = fma2(p2[0][m], w.y, o0b);
                o1a = fma2(p2[1][m], w.x, o1a);  o1b = fma2(p2[1][m], w.y, o1b);
                o2a = fma2(p2[2][m], w.x, o2a);  o2b = fma2(p2[2][m], w.y, o2b);
                o3a = fma2(p2[3][m], w.x, o3a);  o3b = fma2(p2[3][m], w.y, o3b);
            }
            ulonglong2 v0; v0.x = o0a; v0.y = o0b; or0[base + j] = v0;
            ulonglong2 v1; v1.x = o1a; v1.y = o1b; or1[base + j] = v1;
            ulonglong2 v2; v2.x = o2a; v2.y = o2b; or2[base + j] = v2;
            ulonglong2 v3; v3.x = o3a; v3.y = o3b; or3[base + j] = v3;
        }
        __syncthreads();
    }
}

extern "C" void kernel_launch(void* const* d_in, const int* in_sizes, int n_in,
                              void* d_out, int out_size) {
    const float* x   = (const float*)d_in[0];   // [32,256,88,88]
    const float* mem = (const float*)d_in[1];   // [10,88,88]
    float* out = (float*)d_out;                 // [32,256,88,88]

    dim3 grid(ROWS / RPB);     // 256 blocks
    dim3 block(NTHREADS);      // 256 threads
    memaug_fused_kernel<<<grid, block>>>(x, mem, out);
}